// round 15
// baseline (speedup 1.0000x reference)
#include <cuda_runtime.h>

// AnisotropicDistance, folded form (alpha > 0):
//   along = pd_self_i - p_j . t_i
//   out   = max(alpha*sq_i + alpha*sq_j - 2alpha*(pi.pj) + alpha*(tn2-2)*along^2, 0)
//           + beta*along^2
//
// R2: packed f32x2 math (fma.rn.f32x2) to halve fma-pipe issue; per-i constants
// pre-duplicated in smem so no per-iteration broadcast packing; __stcs streaming
// stores. Block tile: 256 j x 32 i; thread tile: 4 j (1 STG.128) x 8 i.

#define TJ 256
#define TI 32
#define IPER 8
#define NTHREADS 256

typedef unsigned long long u64;

__device__ __forceinline__ u64 pk2(float lo, float hi) {
    u64 r; asm("mov.b64 %0, {%1, %2};" : "=l"(r) : "f"(lo), "f"(hi)); return r;
}
__device__ __forceinline__ void upk2(float& lo, float& hi, u64 v) {
    asm("mov.b64 {%0, %1}, %2;" : "=f"(lo), "=f"(hi) : "l"(v));
}
__device__ __forceinline__ u64 fma2(u64 a, u64 b, u64 c) {
    u64 d; asm("fma.rn.f32x2 %0, %1, %2, %3;" : "=l"(d) : "l"(a), "l"(b), "l"(c));
    return d;
}
__device__ __forceinline__ u64 mul2(u64 a, u64 b) {
    u64 d; asm("mul.rn.f32x2 %0, %1, %2;" : "=l"(d) : "l"(a), "l"(b));
    return d;
}

__global__ __launch_bounds__(NTHREADS)
void AnisotropicDistance_kernel(
    const float* __restrict__ points,
    const float* __restrict__ pdir,
    const float* __restrict__ lin,
    float* __restrict__ out,
    int N)
{
    // Per-i constants, each pre-duplicated into both f32x2 lanes.
    // [0..3]  = -tx, -ty, -tz, pd_self
    // [4..7]  = pix, piy, piz, alpha*sq_i
    // [8..11] = alpha, -2*alpha, alpha*(tn2-2), beta
    __shared__ __align__(16) u64 sc[TI][12];

    const int b  = blockIdx.z;
    const int i0 = blockIdx.y * TI;
    const int j0 = blockIdx.x * TJ;
    const int t  = threadIdx.x;

    if (t < TI) {
        const int i = i0 + t;
        const size_t base = ((size_t)b * N + i) * 3;
        const float px = points[base + 0];
        const float py = points[base + 1];
        const float pz = points[base + 2];
        const float tx = pdir[base + 0];
        const float ty = pdir[base + 1];
        const float tz = pdir[base + 2];
        const float l  = lin[(size_t)b * N + i];

        const float alpha   = 2.0f * (1.0f + l);
        const float beta    = 0.5f * (1.0f - l);
        const float pd_self = fmaf(px, tx, fmaf(py, ty, pz * tz));
        const float sq_i    = fmaf(px, px, fmaf(py, py, pz * pz));
        const float tn2     = fmaf(tx, tx, fmaf(ty, ty, tz * tz));

        sc[t][0]  = pk2(-tx, -tx);
        sc[t][1]  = pk2(-ty, -ty);
        sc[t][2]  = pk2(-tz, -tz);
        sc[t][3]  = pk2(pd_self, pd_self);
        sc[t][4]  = pk2(px, px);
        sc[t][5]  = pk2(py, py);
        sc[t][6]  = pk2(pz, pz);
        sc[t][7]  = pk2(alpha * sq_i, alpha * sq_i);
        sc[t][8]  = pk2(alpha, alpha);
        sc[t][9]  = pk2(-2.0f * alpha, -2.0f * alpha);
        sc[t][10] = pk2(alpha * (tn2 - 2.0f), alpha * (tn2 - 2.0f));
        sc[t][11] = pk2(beta, beta);
    }
    __syncthreads();

    // ---- per-thread j quad: 4 consecutive points = 3 aligned float4 loads ----
    const int jt = t & 63;          // 0..63
    const int ig = t >> 6;          // i-group 0..3
    const int j  = j0 + jt * 4;

    const float4* pj4 = reinterpret_cast<const float4*>(points + ((size_t)b * N + j) * 3);
    const float4 q0 = pj4[0];
    const float4 q1 = pj4[1];
    const float4 q2 = pj4[2];

    const float s0 = fmaf(q0.x, q0.x, fmaf(q0.y, q0.y, q0.z * q0.z));
    const float s1 = fmaf(q0.w, q0.w, fmaf(q1.x, q1.x, q1.y * q1.y));
    const float s2 = fmaf(q1.z, q1.z, fmaf(q1.w, q1.w, q2.x * q2.x));
    const float s3 = fmaf(q2.y, q2.y, fmaf(q2.z, q2.z, q2.w * q2.w));

    // Pack j data once: pairs (0,1) and (2,3).
    const u64 px01 = pk2(q0.x, q0.w), px23 = pk2(q1.z, q2.y);
    const u64 py01 = pk2(q0.y, q1.x), py23 = pk2(q1.w, q2.z);
    const u64 pz01 = pk2(q0.z, q1.y), pz23 = pk2(q2.x, q2.w);
    const u64 sq01 = pk2(s0, s1),     sq23 = pk2(s2, s3);

    float* orow = out + ((size_t)b * N + (size_t)(i0 + ig * IPER)) * (size_t)N + j;
    const size_t rowstride = (size_t)N;

#pragma unroll
    for (int ii = 0; ii < IPER; ii++) {
        const u64* ci = sc[ig * IPER + ii];
        const u64 Ax = ci[0], Ay = ci[1], Az = ci[2], Aw = ci[3];
        const u64 Bx = ci[4], By = ci[5], Bz = ci[6], Bw = ci[7];
        const u64 Cx = ci[8], Cy = ci[9], Cz = ci[10], Cw = ci[11];

        // along, dot(pi,pj), along^2, fused linear combo -- all packed
        const u64 al01 = fma2(Ax, px01, fma2(Ay, py01, fma2(Az, pz01, Aw)));
        const u64 al23 = fma2(Ax, px23, fma2(Ay, py23, fma2(Az, pz23, Aw)));
        const u64 dp01 = fma2(Bx, px01, fma2(By, py01, mul2(Bz, pz01)));
        const u64 dp23 = fma2(Bx, px23, fma2(By, py23, mul2(Bz, pz23)));
        const u64 q201 = mul2(al01, al01);
        const u64 q223 = mul2(al23, al23);
        const u64 v01  = fma2(Cz, q201, fma2(Cy, dp01, fma2(Cx, sq01, Bw)));
        const u64 v23  = fma2(Cz, q223, fma2(Cy, dp23, fma2(Cx, sq23, Bw)));

        float beta, beta_hi;
        upk2(beta, beta_hi, Cw);

        float v0, v1, v2, v3, a0, a1, a2, a3;
        upk2(v0, v1, v01); upk2(v2, v3, v23);
        upk2(a0, a1, q201); upk2(a2, a3, q223);

        float4 r;
        r.x = fmaf(beta, a0, fmaxf(v0, 0.0f));
        r.y = fmaf(beta, a1, fmaxf(v1, 0.0f));
        r.z = fmaf(beta, a2, fmaxf(v2, 0.0f));
        r.w = fmaf(beta, a3, fmaxf(v3, 0.0f));

        __stcs(reinterpret_cast<float4*>(orow), r);
        orow += rowstride;
    }
}

extern "C" void kernel_launch(void* const* d_in, const int* in_sizes, int n_in,
                              void* d_out, int out_size)
{
    const float* points = (const float*)d_in[0];
    const float* pdir   = (const float*)d_in[1];
    const float* lin    = (const float*)d_in[2];
    float* out          = (float*)d_out;

    const long long BN = in_sizes[2];
    const int N = (int)((long long)out_size / BN);
    const int B = (int)(BN / N);

    dim3 grid(N / TJ, N / TI, B);
    AnisotropicDistance_kernel<<<grid, NTHREADS>>>(points, pdir, lin, out, N);
}